// round 15
// baseline (speedup 1.0000x reference)
#include <cuda_runtime.h>
#include <cuda_fp16.h>
#include <math.h>
#include <stdint.h>

#define TT 512
#define NN 1024
#define DD 256
#define M_ROWS (TT * NN)

__device__ float g_e[M_ROWS];
__device__ __align__(16) __half g_Whi[DD * DD];
__device__ __align__(16) __half g_Hh[(size_t)M_ROWS * DD];   // fp16 H copy
// attend scan carry (online-softmax state across chunk kernels)
__device__ float g_m[NN];
__device__ float g_s[NN];
__device__ __align__(16) float g_num[NN * DD];

// ---------------------------------------------------------------------------
// SMEM (per CTA, 57344 B -> 3 CTAs/SM = 168 KB; attend block adds 1.2 KB).
// ---------------------------------------------------------------------------
#define SA_OFF  0
#define SA_ROW  528
#define SB_OFF  33792
#define SB_SZ   10240
#define SBIAS   54272
#define SSW     55296
#define SRED    56320
#define SMTOT   57344

// ---------------------------------------------------------------------------
// PTX helpers (baseline ISA only -- toolchain targets sm_103, no tcgen05)
// ---------------------------------------------------------------------------
__device__ __forceinline__ uint32_t smem_u32(const void* p) {
    uint32_t a;
    asm("{ .reg .u64 t; cvta.to.shared.u64 t, %1; cvt.u32.u64 %0, t; }"
        : "=r"(a) : "l"(p));
    return a;
}
__device__ __forceinline__ void cp_async16(uint32_t dst, const void* src) {
    asm volatile("cp.async.cg.shared.global [%0], [%1], 16;"
                 :: "r"(dst), "l"(src) : "memory");
}
#define CP_COMMIT() asm volatile("cp.async.commit_group;" ::: "memory")
#define CP_WAIT(n)  asm volatile("cp.async.wait_group %0;" :: "n"(n) : "memory")

__device__ __forceinline__ void ldsm4(uint32_t* r, uint32_t addr) {
    asm volatile("ldmatrix.sync.aligned.m8n8.x4.shared.b16 {%0,%1,%2,%3}, [%4];"
                 : "=r"(r[0]), "=r"(r[1]), "=r"(r[2]), "=r"(r[3]) : "r"(addr));
}
__device__ __forceinline__ void mma16816(float* c, const uint32_t* a,
                                         uint32_t b0, uint32_t b1) {
    asm volatile(
        "mma.sync.aligned.m16n8k16.row.col.f32.f16.f16.f32 "
        "{%0,%1,%2,%3}, {%4,%5,%6,%7}, {%8,%9}, {%0,%1,%2,%3};"
        : "+f"(c[0]), "+f"(c[1]), "+f"(c[2]), "+f"(c[3])
        : "r"(a[0]), "r"(a[1]), "r"(a[2]), "r"(a[3]), "r"(b0), "r"(b1));
}

// fp32 x8 -> fp16 x8
__device__ __forceinline__ uint4 cvt8hi(const float4& u, const float4& v) {
    __half2 h0 = __floats2half2_rn(u.x, u.y);
    __half2 h1 = __floats2half2_rn(u.z, u.w);
    __half2 h2 = __floats2half2_rn(v.x, v.y);
    __half2 h3 = __floats2half2_rn(v.z, v.w);
    uint4 hi;
    hi.x = *(uint32_t*)&h0; hi.y = *(uint32_t*)&h1;
    hi.z = *(uint32_t*)&h2; hi.w = *(uint32_t*)&h3;
    return hi;
}

// tanh via MUFU (EX2 + RCP), rel err ~1e-6
__device__ __forceinline__ float tanh_mufu(float z) {
    float u = __expf(2.0f * z);
    return 1.0f - __fdividef(2.0f, u + 1.0f);
}

// ---------------------------------------------------------------------------
__global__ void w_prep(const float* __restrict__ W) {
    int i = blockIdx.x * blockDim.x + threadIdx.x;
    const float4* p = reinterpret_cast<const float4*>(W) + i * 2;
    reinterpret_cast<uint4*>(g_Whi)[i] = cvt8hi(p[0], p[1]);
}

// ---------------------------------------------------------------------------
// Kernel A: fp16 HMMA GEMM, BM=64 x BN=256 in two 128-col passes.
// 256 threads, 3 CTAs/SM (regs must stay ~80: the 4.1K-reg leftover hosts
// the co-resident attend block). Adds fp16-H writeback in pass-0 prologue.
// ---------------------------------------------------------------------------
__global__ __launch_bounds__(256, 3)
void gemm_score_hmma(const float* __restrict__ H,
                     const float* __restrict__ bias,
                     const float* __restrict__ swt,
                     int blk0)
{
    extern __shared__ char smem[];
    const uint32_t sb = smem_u32(smem);
    const int tid  = threadIdx.x;
    const int lane = tid & 31;
    const int warp = tid >> 5;          // 0..7
    const int wr   = warp & 1;          // row group 32*wr
    const int wc   = warp >> 1;         // col group 32*wc (within pass)
    const int row0 = (blockIdx.x + blk0) * 64;

    ((float*)(smem + SBIAS))[tid] = bias[tid];
    ((float*)(smem + SSW))[tid]   = swt[tid];

    const int lrow = lane & 15;
    const int lkh  = lane >> 4;
    const uint32_t aAddr = sb + SA_OFF +
                           (uint32_t)((wr * 32 + lrow) * SA_ROW + lkh * 16);
    const uint32_t bAddr = sb + SB_OFF +
                           (uint32_t)((wc * 32 + lrow) * 80 + lkh * 16);

    const float* sbias = (const float*)(smem + SBIAS);
    const float* ssw   = (const float*)(smem + SSW);

    float partAcc[2][2] = {{0.0f, 0.0f}, {0.0f, 0.0f}};

    #pragma unroll 1
    for (int pass = 0; pass < 2; pass++) {
        const __half* Bsrc = g_Whi + (size_t)pass * 128 * DD;

        auto cpB = [&](int c, int buf) {
            #pragma unroll
            for (int p = 0; p < 2; p++) {
                int idx = tid + p * 256;
                int r   = idx >> 2;
                int ch  = idx & 3;
                cp_async16(sb + SB_OFF + buf * SB_SZ + r * 80 + ch * 16,
                           Bsrc + (size_t)r * DD + c * 32 + ch * 8);
            }
            CP_COMMIT();
        };

        cpB(0, 0);
        if (pass == 0) {
            // A convert: 64 rows x 256 k -> fp16 SMEM + fp16 gmem copy
            #pragma unroll
            for (int i = 0; i < 8; i++) {
                int slot = tid + i * 256;
                int r    = slot >> 5;
                int kseg = slot & 31;
                const float* src = H + (size_t)(row0 + r) * DD + kseg * 8;
                float4 u = *reinterpret_cast<const float4*>(src);
                float4 v = *reinterpret_cast<const float4*>(src + 4);
                uint4 hv = cvt8hi(u, v);
                *reinterpret_cast<uint4*>(smem + SA_OFF + r * SA_ROW +
                                          kseg * 16) = hv;
                reinterpret_cast<uint4*>(g_Hh)[(size_t)(row0 + r) * 32 +
                                               kseg] = hv;
            }
        }
        CP_WAIT(0);
        __syncthreads();

        float acc[2][4][4];
        #pragma unroll
        for (int m = 0; m < 2; m++)
            #pragma unroll
            for (int j = 0; j < 4; j++)
                #pragma unroll
                for (int e = 0; e < 4; e++) acc[m][j][e] = 0.0f;

        #pragma unroll
        for (int c = 0; c < 8; c++) {
            const int buf = c & 1;
            if (c < 7) cpB(c + 1, buf ^ 1);

            const uint32_t aA = aAddr + (uint32_t)(c * 64);
            const uint32_t bB = bAddr + (uint32_t)(buf * SB_SZ);
            #pragma unroll
            for (int ks = 0; ks < 2; ks++) {
                uint32_t ah[2][4];
                ldsm4(ah[0], aA + ks * 32);
                ldsm4(ah[1], aA + 16 * SA_ROW + ks * 32);
                #pragma unroll
                for (int ntp = 0; ntp < 2; ntp++) {
                    uint32_t bf[4];
                    ldsm4(bf, bB + ntp * (16 * 80) + ks * 32);
                    #pragma unroll
                    for (int mt = 0; mt < 2; mt++) {
                        mma16816(acc[mt][ntp * 2 + 0], ah[mt], bf[0], bf[2]);
                        mma16816(acc[mt][ntp * 2 + 1], ah[mt], bf[1], bf[3]);
                    }
                }
            }
            if (c < 7) {
                CP_WAIT(0);
                __syncthreads();
            }
        }

        #pragma unroll
        for (int mt = 0; mt < 2; mt++) {
            #pragma unroll
            for (int h = 0; h < 2; h++) {
                float part = 0.0f;
                #pragma unroll
                for (int j = 0; j < 4; j++) {
                    const int col = pass * 128 + wc * 32 + j * 8 +
                                    (lane & 3) * 2;
                    float2 bb = *reinterpret_cast<const float2*>(&sbias[col]);
                    float2 ws = *reinterpret_cast<const float2*>(&ssw[col]);
                    part = fmaf(tanh_mufu(acc[mt][j][h * 2 + 0] + bb.x),
                                ws.x, part);
                    part = fmaf(tanh_mufu(acc[mt][j][h * 2 + 1] + bb.y),
                                ws.y, part);
                }
                partAcc[mt][h] += part;
            }
        }
    }

    float* sred = (float*)(smem + SRED);
    #pragma unroll
    for (int mt = 0; mt < 2; mt++) {
        #pragma unroll
        for (int h = 0; h < 2; h++) {
            float part = partAcc[mt][h];
            part += __shfl_xor_sync(0xffffffffu, part, 1);
            part += __shfl_xor_sync(0xffffffffu, part, 2);
            const int lrow_out = wr * 32 + mt * 16 + (lane >> 2) + h * 8;
            if ((lane & 3) == 0) sred[wc * 64 + lrow_out] = part;
        }
    }
    __syncthreads();
    if (tid < 64)
        g_e[row0 + tid] = (sred[tid] + sred[64 + tid]) +
                          (sred[128 + tid] + sred[192 + tid]);
}

// ---------------------------------------------------------------------------
// Kernel B: chunked causal softmax prefix average over fp16 H copy.
// R13 shape: 64 threads, 1 chain-group per thread (now 4 d's via uint2
// fp16 load), <=64 regs so one block co-resides beside 3 GEMM CTAs.
// ---------------------------------------------------------------------------
__global__ __launch_bounds__(64, 16)
void attend_chunk(float* __restrict__ C, int t0, int t1, int first)
{
    __shared__ float sal[96];   // alpha
    __shared__ float sp[96];    // p
    __shared__ float siv[96];   // 1/s

    const int n   = blockIdx.x;
    const int tid = threadIdx.x;
    const int len = t1 - t0;

    for (int i = tid; i < len; i += 64)
        sal[i] = g_e[(size_t)(t0 + i) * NN + n];
    __syncthreads();

    if (tid == 0) {
        float m = first ? -INFINITY : g_m[n];
        float s = first ? 0.0f      : g_s[n];
        for (int i = 0; i < len; i++) {
            float e  = sal[i];
            float mn = fmaxf(m, e);
            float a  = __expf(m - mn);
            float p  = __expf(e - mn);
            s = s * a + p;
            sal[i] = a;
            sp[i]  = p;
            siv[i] = __fdividef(1.0f, s);
            m = mn;
        }
        g_m[n] = m;
        g_s[n] = s;
    }
    __syncthreads();

    // 64 uint2 (4 halves) per (t, n) row; thread owns uint2 slot tid.
    const size_t strideH = (size_t)NN * 64;        // uint2 units per t
    const size_t strideC = (size_t)NN * 64;        // float4 units per t
    const uint2* hp = reinterpret_cast<const uint2*>(g_Hh) +
                      (size_t)t0 * strideH + (size_t)n * 64 + tid;
    float4* cp = reinterpret_cast<float4*>(C) +
                 (size_t)t0 * strideC + (size_t)n * 64 + tid;
    float4* gn = reinterpret_cast<float4*>(g_num) + (size_t)n * 64 + tid;

    float4 num;
    if (first) num = make_float4(0.f, 0.f, 0.f, 0.f);
    else       num = *gn;

    #pragma unroll 8
    for (int i = 0; i < len; i++) {
        uint2 hv = __ldcs(hp + (size_t)i * strideH);
        __half2 ha = *reinterpret_cast<__half2*>(&hv.x);
        __half2 hb = *reinterpret_cast<__half2*>(&hv.y);
        float2 f0 = __half22float2(ha);
        float2 f1 = __half22float2(hb);
        float a = sal[i], p = sp[i], si = siv[i];
        num.x = fmaf(num.x, a, p * f0.x);
        num.y = fmaf(num.y, a, p * f0.y);
        num.z = fmaf(num.z, a, p * f1.x);
        num.w = fmaf(num.w, a, p * f1.y);
        float4 o = make_float4(num.x * si, num.y * si, num.z * si, num.w * si);
        __stcs(cp + (size_t)i * strideC, o);
    }
    *gn = num;
}

// ---------------------------------------------------------------------------
// Stream/event plumbing (global ctor; no device-memory APIs).
// ---------------------------------------------------------------------------
#define NCHUNK 8
namespace {
struct Plumbing {
    cudaStream_t s2;
    cudaEvent_t  evG[NCHUNK];
    cudaEvent_t  evJ;
    Plumbing() {
        int lo = 0, hi = 0;
        cudaDeviceGetStreamPriorityRange(&lo, &hi);
        cudaStreamCreateWithPriority(&s2, cudaStreamNonBlocking, hi);
        for (int i = 0; i < NCHUNK; i++)
            cudaEventCreateWithFlags(&evG[i], cudaEventDisableTiming);
        cudaEventCreateWithFlags(&evJ, cudaEventDisableTiming);
    }
};
Plumbing g_plumb;
}

// 3 CTAs/SM -> 444 blocks/wave; chunks of 1328 (~3 waves, /16-aligned).
static const int kBlk[NCHUNK + 1] =
    {0, 1328, 2656, 3984, 5312, 6640, 7968, 8096, 8192};

// ---------------------------------------------------------------------------
extern "C" void kernel_launch(void* const* d_in, const int* in_sizes, int n_in,
                              void* d_out, int out_size)
{
    const float* H  = (const float*)d_in[0];
    const float* W  = (const float*)d_in[1];
    const float* b  = (const float*)d_in[2];
    const float* sv = (const float*)d_in[3];
    float* C = (float*)d_out;

    cudaFuncSetAttribute(gemm_score_hmma,
                         cudaFuncAttributeMaxDynamicSharedMemorySize, SMTOT);

    w_prep<<<16, 512>>>(W);

    for (int c = 0; c < NCHUNK; c++) {
        gemm_score_hmma<<<kBlk[c + 1] - kBlk[c], 256, SMTOT>>>(H, b, sv, kBlk[c]);
        cudaEventRecord(g_plumb.evG[c], 0);
    }
    for (int c = 0; c < NCHUNK; c++) {
        cudaStreamWaitEvent(g_plumb.s2, g_plumb.evG[c], 0);
        attend_chunk<<<NN, 64, 0, g_plumb.s2>>>(C, kBlk[c] / 16,
                                                kBlk[c + 1] / 16, c == 0);
    }
    cudaEventRecord(g_plumb.evJ, g_plumb.s2);
    cudaStreamWaitEvent(0, g_plumb.evJ, 0);
}

// round 17
// speedup vs baseline: 1.0667x; 1.0667x over previous
#include <cuda_runtime.h>
#include <cuda_fp16.h>
#include <math.h>
#include <stdint.h>

#define TT 512
#define NN 1024
#define DD 256
#define M_ROWS (TT * NN)

__device__ float g_e[M_ROWS];
__device__ __align__(16) __half g_Whi[DD * DD];
// attend scan carry (online-softmax state across chunk kernels)
__device__ float g_m[NN];
__device__ float g_s[NN];
__device__ __align__(16) float g_num[NN * DD];

// ---------------------------------------------------------------------------
// SMEM (per CTA, 57344 B -> 3 CTAs/SM = 168 KB; attend block adds 1.2 KB).
// ---------------------------------------------------------------------------
#define SA_OFF  0
#define SA_ROW  528
#define SB_OFF  33792
#define SB_SZ   10240
#define SBIAS   54272
#define SSW     55296
#define SRED    56320
#define SMTOT   57344

// ---------------------------------------------------------------------------
// PTX helpers (baseline ISA only -- toolchain targets sm_103, no tcgen05)
// ---------------------------------------------------------------------------
__device__ __forceinline__ uint32_t smem_u32(const void* p) {
    uint32_t a;
    asm("{ .reg .u64 t; cvta.to.shared.u64 t, %1; cvt.u32.u64 %0, t; }"
        : "=r"(a) : "l"(p));
    return a;
}
__device__ __forceinline__ void cp_async16(uint32_t dst, const void* src) {
    asm volatile("cp.async.cg.shared.global [%0], [%1], 16;"
                 :: "r"(dst), "l"(src) : "memory");
}
#define CP_COMMIT() asm volatile("cp.async.commit_group;" ::: "memory")
#define CP_WAIT(n)  asm volatile("cp.async.wait_group %0;" :: "n"(n) : "memory")

__device__ __forceinline__ void ldsm4(uint32_t* r, uint32_t addr) {
    asm volatile("ldmatrix.sync.aligned.m8n8.x4.shared.b16 {%0,%1,%2,%3}, [%4];"
                 : "=r"(r[0]), "=r"(r[1]), "=r"(r[2]), "=r"(r[3]) : "r"(addr));
}
__device__ __forceinline__ void mma16816(float* c, const uint32_t* a,
                                         uint32_t b0, uint32_t b1) {
    asm volatile(
        "mma.sync.aligned.m16n8k16.row.col.f32.f16.f16.f32 "
        "{%0,%1,%2,%3}, {%4,%5,%6,%7}, {%8,%9}, {%0,%1,%2,%3};"
        : "+f"(c[0]), "+f"(c[1]), "+f"(c[2]), "+f"(c[3])
        : "r"(a[0]), "r"(a[1]), "r"(a[2]), "r"(a[3]), "r"(b0), "r"(b1));
}

// fp32 x8 -> fp16 x8
__device__ __forceinline__ uint4 cvt8hi(const float4& u, const float4& v) {
    __half2 h0 = __floats2half2_rn(u.x, u.y);
    __half2 h1 = __floats2half2_rn(u.z, u.w);
    __half2 h2 = __floats2half2_rn(v.x, v.y);
    __half2 h3 = __floats2half2_rn(v.z, v.w);
    uint4 hi;
    hi.x = *(uint32_t*)&h0; hi.y = *(uint32_t*)&h1;
    hi.z = *(uint32_t*)&h2; hi.w = *(uint32_t*)&h3;
    return hi;
}

// tanh via MUFU (EX2 + RCP), rel err ~1e-6
__device__ __forceinline__ float tanh_mufu(float z) {
    float u = __expf(2.0f * z);
    return 1.0f - __fdividef(2.0f, u + 1.0f);
}

// ---------------------------------------------------------------------------
__global__ void w_prep(const float* __restrict__ W) {
    int i = blockIdx.x * blockDim.x + threadIdx.x;
    const float4* p = reinterpret_cast<const float4*>(W) + i * 2;
    reinterpret_cast<uint4*>(g_Whi)[i] = cvt8hi(p[0], p[1]);
}

// ---------------------------------------------------------------------------
// Kernel A: fp16 HMMA GEMM, BM=64 x BN=256 in two 128-col passes.
// 256 threads, 3 CTAs/SM. IDENTICAL to R13 (regs=80 defines the leftover
// register pool the attend block lives in -- do not perturb).
// ---------------------------------------------------------------------------
__global__ __launch_bounds__(256, 3)
void gemm_score_hmma(const float* __restrict__ H,
                     const float* __restrict__ bias,
                     const float* __restrict__ swt,
                     int blk0)
{
    extern __shared__ char smem[];
    const uint32_t sb = smem_u32(smem);
    const int tid  = threadIdx.x;
    const int lane = tid & 31;
    const int warp = tid >> 5;          // 0..7
    const int wr   = warp & 1;          // row group 32*wr
    const int wc   = warp >> 1;         // col group 32*wc (within pass)
    const int row0 = (blockIdx.x + blk0) * 64;

    ((float*)(smem + SBIAS))[tid] = bias[tid];
    ((float*)(smem + SSW))[tid]   = swt[tid];

    const int lrow = lane & 15;
    const int lkh  = lane >> 4;
    const uint32_t aAddr = sb + SA_OFF +
                           (uint32_t)((wr * 32 + lrow) * SA_ROW + lkh * 16);
    const uint32_t bAddr = sb + SB_OFF +
                           (uint32_t)((wc * 32 + lrow) * 80 + lkh * 16);

    const float* sbias = (const float*)(smem + SBIAS);
    const float* ssw   = (const float*)(smem + SSW);

    float partAcc[2][2] = {{0.0f, 0.0f}, {0.0f, 0.0f}};

    #pragma unroll 1
    for (int pass = 0; pass < 2; pass++) {
        const __half* Bsrc = g_Whi + (size_t)pass * 128 * DD;

        auto cpB = [&](int c, int buf) {
            #pragma unroll
            for (int p = 0; p < 2; p++) {
                int idx = tid + p * 256;
                int r   = idx >> 2;
                int ch  = idx & 3;
                cp_async16(sb + SB_OFF + buf * SB_SZ + r * 80 + ch * 16,
                           Bsrc + (size_t)r * DD + c * 32 + ch * 8);
            }
            CP_COMMIT();
        };

        cpB(0, 0);
        if (pass == 0) {
            #pragma unroll
            for (int i = 0; i < 8; i++) {
                int slot = tid + i * 256;
                int r    = slot >> 5;
                int kseg = slot & 31;
                const float* src = H + (size_t)(row0 + r) * DD + kseg * 8;
                float4 u = *reinterpret_cast<const float4*>(src);
                float4 v = *reinterpret_cast<const float4*>(src + 4);
                *reinterpret_cast<uint4*>(smem + SA_OFF + r * SA_ROW +
                                          kseg * 16) = cvt8hi(u, v);
            }
        }
        CP_WAIT(0);
        __syncthreads();

        float acc[2][4][4];
        #pragma unroll
        for (int m = 0; m < 2; m++)
            #pragma unroll
            for (int j = 0; j < 4; j++)
                #pragma unroll
                for (int e = 0; e < 4; e++) acc[m][j][e] = 0.0f;

        #pragma unroll
        for (int c = 0; c < 8; c++) {
            const int buf = c & 1;
            if (c < 7) cpB(c + 1, buf ^ 1);

            const uint32_t aA = aAddr + (uint32_t)(c * 64);
            const uint32_t bB = bAddr + (uint32_t)(buf * SB_SZ);
            #pragma unroll
            for (int ks = 0; ks < 2; ks++) {
                uint32_t ah[2][4];
                ldsm4(ah[0], aA + ks * 32);
                ldsm4(ah[1], aA + 16 * SA_ROW + ks * 32);
                #pragma unroll
                for (int ntp = 0; ntp < 2; ntp++) {
                    uint32_t bf[4];
                    ldsm4(bf, bB + ntp * (16 * 80) + ks * 32);
                    #pragma unroll
                    for (int mt = 0; mt < 2; mt++) {
                        mma16816(acc[mt][ntp * 2 + 0], ah[mt], bf[0], bf[2]);
                        mma16816(acc[mt][ntp * 2 + 1], ah[mt], bf[1], bf[3]);
                    }
                }
            }
            if (c < 7) {
                CP_WAIT(0);
                __syncthreads();
            }
        }

        #pragma unroll
        for (int mt = 0; mt < 2; mt++) {
            #pragma unroll
            for (int h = 0; h < 2; h++) {
                float part = 0.0f;
                #pragma unroll
                for (int j = 0; j < 4; j++) {
                    const int col = pass * 128 + wc * 32 + j * 8 +
                                    (lane & 3) * 2;
                    float2 bb = *reinterpret_cast<const float2*>(&sbias[col]);
                    float2 ws = *reinterpret_cast<const float2*>(&ssw[col]);
                    part = fmaf(tanh_mufu(acc[mt][j][h * 2 + 0] + bb.x),
                                ws.x, part);
                    part = fmaf(tanh_mufu(acc[mt][j][h * 2 + 1] + bb.y),
                                ws.y, part);
                }
                partAcc[mt][h] += part;
            }
        }
    }

    float* sred = (float*)(smem + SRED);
    #pragma unroll
    for (int mt = 0; mt < 2; mt++) {
        #pragma unroll
        for (int h = 0; h < 2; h++) {
            float part = partAcc[mt][h];
            part += __shfl_xor_sync(0xffffffffu, part, 1);
            part += __shfl_xor_sync(0xffffffffu, part, 2);
            const int lrow_out = wr * 32 + mt * 16 + (lane >> 2) + h * 8;
            if ((lane & 3) == 0) sred[wc * 64 + lrow_out] = part;
        }
    }
    __syncthreads();
    if (tid < 64)
        g_e[row0 + tid] = (sred[tid] + sred[64 + tid]) +
                          (sred[128 + tid] + sred[192 + tid]);
}

// ---------------------------------------------------------------------------
// Kernel B: chunked causal softmax prefix average (fp32 H).
// 128 threads x float2 per thread; launch_bounds(128,16) caps regs at 32 so
// the block (4K regs) co-resides beside 3 GEMM CTAs, using all 4 SMSPs and
// 4 warps of load concurrency.
// ---------------------------------------------------------------------------
__global__ __launch_bounds__(128, 16)
void attend_chunk(const float* __restrict__ H, float* __restrict__ C,
                  int t0, int t1, int first)
{
    __shared__ float sal[96];   // alpha
    __shared__ float sp[96];    // p
    __shared__ float siv[96];   // 1/s

    const int n   = blockIdx.x;
    const int tid = threadIdx.x;
    const int len = t1 - t0;

    for (int i = tid; i < len; i += 128)
        sal[i] = g_e[(size_t)(t0 + i) * NN + n];
    __syncthreads();

    if (tid == 0) {
        float m = first ? -INFINITY : g_m[n];
        float s = first ? 0.0f      : g_s[n];
        for (int i = 0; i < len; i++) {
            float e  = sal[i];
            float mn = fmaxf(m, e);
            float a  = __expf(m - mn);
            float p  = __expf(e - mn);
            s = s * a + p;
            sal[i] = a;
            sp[i]  = p;
            siv[i] = __fdividef(1.0f, s);
            m = mn;
        }
        g_m[n] = m;
        g_s[n] = s;
    }
    __syncthreads();

    const size_t stride2 = (size_t)NN * (DD / 2);   // float2 units per t
    const float2* hp = reinterpret_cast<const float2*>(H) +
                       (size_t)t0 * stride2 + (size_t)n * (DD / 2) + tid;
    float2* cp = reinterpret_cast<float2*>(C) +
                 (size_t)t0 * stride2 + (size_t)n * (DD / 2) + tid;
    float2* gn = reinterpret_cast<float2*>(g_num) + (size_t)n * (DD / 2) + tid;

    float2 num;
    if (first) num = make_float2(0.f, 0.f);
    else       num = *gn;

    #pragma unroll 8
    for (int i = 0; i < len; i++) {
        float2 h = __ldcs(hp + (size_t)i * stride2);
        float a = sal[i], p = sp[i], si = siv[i];
        num.x = fmaf(num.x, a, p * h.x);
        num.y = fmaf(num.y, a, p * h.y);
        float2 o = make_float2(num.x * si, num.y * si);
        __stcs(cp + (size_t)i * stride2, o);
    }
    *gn = num;
}

// ---------------------------------------------------------------------------
// Stream/event plumbing (global ctor; no device-memory APIs).
// ---------------------------------------------------------------------------
#define NCHUNK 8
namespace {
struct Plumbing {
    cudaStream_t s2;
    cudaEvent_t  evG[NCHUNK];
    cudaEvent_t  evJ;
    Plumbing() {
        int lo = 0, hi = 0;
        cudaDeviceGetStreamPriorityRange(&lo, &hi);
        cudaStreamCreateWithPriority(&s2, cudaStreamNonBlocking, hi);
        for (int i = 0; i < NCHUNK; i++)
            cudaEventCreateWithFlags(&evG[i], cudaEventDisableTiming);
        cudaEventCreateWithFlags(&evJ, cudaEventDisableTiming);
    }
};
Plumbing g_plumb;
}

// Tapered chunks (all /16): tiny head (fast first window), tapered tail
// (small final attend exposure). Sizes: 160,1456x4,1280,640,288.
static const int kBlk[NCHUNK + 1] =
    {0, 160, 1616, 3072, 4528, 5984, 7264, 7904, 8192};

// ---------------------------------------------------------------------------
extern "C" void kernel_launch(void* const* d_in, const int* in_sizes, int n_in,
                              void* d_out, int out_size)
{
    const float* H  = (const float*)d_in[0];
    const float* W  = (const float*)d_in[1];
    const float* b  = (const float*)d_in[2];
    const float* sv = (const float*)d_in[3];
    float* C = (float*)d_out;

    cudaFuncSetAttribute(gemm_score_hmma,
                         cudaFuncAttributeMaxDynamicSharedMemorySize, SMTOT);

    w_prep<<<16, 512>>>(W);

    for (int c = 0; c < NCHUNK; c++) {
        gemm_score_hmma<<<kBlk[c + 1] - kBlk[c], 256, SMTOT>>>(H, b, sv, kBlk[c]);
        cudaEventRecord(g_plumb.evG[c], 0);
    }
    for (int c = 0; c < NCHUNK; c++) {
        cudaStreamWaitEvent(g_plumb.s2, g_plumb.evG[c], 0);
        attend_chunk<<<NN, 128, 0, g_plumb.s2>>>(H, C, kBlk[c] / 16,
                                                 kBlk[c + 1] / 16, c == 0);
    }
    cudaEventRecord(g_plumb.evJ, g_plumb.s2);
    cudaStreamWaitEvent(0, g_plumb.evJ, 0);
}